// round 15
// baseline (speedup 1.0000x reference)
#include <cuda_runtime.h>

// LSTM seq2seq: B=64, T=512, F=64, H=512, FUT=96 — persistent v9.
// Encoder role-split: blocks 0-63 run L0 only (producer, races ahead on its own
// 64-block barrier, publishes y0 watermark genA); blocks 64-127 run L1 only
// (consumer: waits genA, x-phase on y0[t], B-barrier hidden behind x-phase,
// h-phase on h1[t-1]). Halves the serial per-slot critical path.
// Decoder and inner-loop math = v5 (best: 14559us) verbatim.

#define BB 64
#define TT 512
#define FF 64
#define HH 512
#define FUT 96
#define BH (BB*HH)          // 32768

typedef unsigned long long u64;

// ---- encoder (role-split) constants: 8 j per block, 256 threads ----
#define ETHR 256
#define WSSE 513            // u2 stride per j (K=512): jl*4 mod 32 distinct
#define WXE  65             // u2 stride per j (K=64)
#define EHSP 68             // floats per staged act row
#define EHSBUF (64*EHSP)    // 4352 floats per buffer
#define ENC_SMEM ((16*WSSE)*16 + 2*EHSBUF*4)        // B-group max: 166144

// ---- decoder (v5) constants: 4 j per block, 128 threads ----
#define DNBLK 128
#define DTHR 128
#define DWSS 514
#define DWSS64 66
#define DHSP 68
#define DHSBUF (64*DHSP)
#define DEC_SMEM ((4*4*DWSS + 4*DWSS64)*16 + 2*DHSBUF*4)   // 170624

// ---------------- device scratch ----------------
__device__ float  g_y0[TT*BB*HH];
__device__ float  g_h1hist[FUT*BB*HH];
__device__ float  g_zero[BH];
__device__ float  g_c0[BH], g_c1[BH];
__device__ float  g_h1A[BH], g_h1B[BH], g_h0A[BH], g_h0B[BH];

// pair-packed weights: per (j,k2): float4 {i(k),i(k+1),f(k),f(k+1)}, {g..,o..}
__device__ float4 g_pW_enc_ih0[HH*FF];
__device__ float4 g_pW_enc_hh0[HH*HH];
__device__ float4 g_pW_enc_ih1[HH*HH];
__device__ float4 g_pW_enc_hh1[HH*HH];
__device__ float4 g_pW_dec_ih0[HH*FF];
__device__ float4 g_pW_dec_hh0[HH*HH];
__device__ float4 g_pW_dec_ih1[HH*HH];
__device__ float4 g_pW_dec_hh1[HH*HH];
__device__ float4 g_pW_dec0c[HH*HH];
__device__ float4 g_pb_enc0[HH], g_pb_enc1[HH], g_pb_dec0[HH], g_pb_dec1[HH], g_pb_dec0c[HH];

// barriers
__device__ unsigned g_bgen;            // decoder 128-block barrier
__device__ unsigned g_flag[DNBLK*8];
__device__ unsigned g_genA;            // y0 watermark (A group)
__device__ unsigned g_flagA[64*8];
__device__ unsigned g_genB;            // h1 barrier gen (B group)
__device__ unsigned g_flagB[64*8];

// ---------------- f32x2 helpers ----------------
__device__ __forceinline__ u64 pack2(float a, float b) {
    u64 r;
    asm("mov.b64 %0, {%1, %2};" : "=l"(r) : "r"(__float_as_uint(a)), "r"(__float_as_uint(b)));
    return r;
}
__device__ __forceinline__ float2 unpack2(u64 v) {
    unsigned int lo, hi;
    asm("mov.b64 {%0, %1}, %2;" : "=r"(lo), "=r"(hi) : "l"(v));
    return make_float2(__uint_as_float(lo), __uint_as_float(hi));
}
__device__ __forceinline__ void ffma2(u64& d, u64 a, u64 b) {
    asm("fma.rn.f32x2 %0, %1, %2, %0;" : "+l"(d) : "l"(a), "l"(b));
}
__device__ __forceinline__ unsigned ld_acq(const unsigned* p) {
    unsigned v;
    asm volatile("ld.acquire.gpu.u32 %0, [%1];" : "=r"(v) : "l"(p));
    return v;
}
__device__ __forceinline__ void st_rel(unsigned* p, unsigned v) {
    asm volatile("st.release.gpu.u32 [%0], %1;" :: "l"(p), "r"(v));
}

// ---------------- shared cell math (v5) ----------------
// A[0..3] = row0 gates i,f,g,o (each u64 = 2 k-lane partials); A[4..7] = row1.
__device__ __forceinline__ void bias_init(u64* A, float4 b) {
    A[0] = pack2(b.x, 0.f); A[1] = pack2(b.y, 0.f);
    A[2] = pack2(b.z, 0.f); A[3] = pack2(b.w, 0.f);
    A[4] = A[0]; A[5] = A[1]; A[6] = A[2]; A[7] = A[3];
}
__device__ __forceinline__ float cellfin4(u64 gi2, u64 gf2, u64 gg2, u64 go2, float& c) {
    float2 vi = unpack2(gi2), vf = unpack2(gf2), vg = unpack2(gg2), vo = unpack2(go2);
    float gi = vi.x + vi.y, gf = vf.x + vf.y, gg = vg.x + vg.y, go = vo.x + vo.y;
    float si = 1.f / (1.f + __expf(-gi));
    float sf = 1.f / (1.f + __expf(-gf));
    float so = 1.f / (1.f + __expf(-go));
    float cn = sf * c + si * tanhf(gg);
    c = cn;
    return so * tanhf(cn);
}
// 64-k chunk, 2 rows per thread (v5 chunk16 verbatim).
__device__ __forceinline__ void chunk16(
    u64* __restrict__ A, const ulonglong2* __restrict__ w,
    const float* __restrict__ h0, const float* __restrict__ h1)
{
#pragma unroll
    for (int k2 = 0; k2 < 32; k2 += 2) {
        ulonglong2 a = *(const ulonglong2*)(h0 + k2 * 2);
        ulonglong2 b = *(const ulonglong2*)(h1 + k2 * 2);
        ulonglong2 wif0 = w[2 * k2 + 0];
        ulonglong2 wgo0 = w[2 * k2 + 1];
        ulonglong2 wif1 = w[2 * k2 + 2];
        ulonglong2 wgo1 = w[2 * k2 + 3];
        ffma2(A[0], a.x, wif0.x); ffma2(A[1], a.x, wif0.y);
        ffma2(A[2], a.x, wgo0.x); ffma2(A[3], a.x, wgo0.y);
        ffma2(A[4], b.x, wif0.x); ffma2(A[5], b.x, wif0.y);
        ffma2(A[6], b.x, wgo0.x); ffma2(A[7], b.x, wgo0.y);
        ffma2(A[0], a.y, wif1.x); ffma2(A[1], a.y, wif1.y);
        ffma2(A[2], a.y, wgo1.x); ffma2(A[3], a.y, wgo1.y);
        ffma2(A[4], b.y, wif1.x); ffma2(A[5], b.y, wif1.y);
        ffma2(A[6], b.y, wgo1.x); ffma2(A[7], b.y, wgo1.y);
    }
}

// ================= encoder phases (256 threads, 8 j) =================
// x: [64][128 float4] row-major (y0 slot / h1 buffer). jl=tid&7, rh=tid>>3.
__device__ __forceinline__ void ephase512(
    u64* __restrict__ A, const float* __restrict__ x,
    const ulonglong2* __restrict__ W, float* hs, int tid, int jl, int rh)
{
    const float4* x4 = (const float4*)x;
    int r = tid & 63, qg = tid >> 6;
    const float4* xr = x4 + (size_t)r * 128 + qg * 4;
    float4 pf[4];
#pragma unroll
    for (int u = 0; u < 4; u++) pf[u] = xr[u];
#pragma unroll 1
    for (int c = 0; c < 8; c++) {
        float* buf = hs + (c & 1) * EHSBUF;
        float4* b4 = (float4*)buf;
#pragma unroll
        for (int u = 0; u < 4; u++) b4[r * 17 + qg * 4 + u] = pf[u];
        __syncthreads();
        if (c < 7) {
#pragma unroll
            for (int u = 0; u < 4; u++) pf[u] = xr[(c + 1) * 16 + u];
        }
        chunk16(A, W + jl * WSSE + c * 64, buf + rh * EHSP, buf + (rh + 32) * EHSP);
    }
}
// K=64 input projection; x rows stride 8192 float4 (in_seq [64][512][64]).
__device__ __forceinline__ void ephase64(
    u64* __restrict__ A, const float* __restrict__ x,
    const ulonglong2* __restrict__ W, float* hs, int tid, int jl, int rh)
{
    const float4* x4 = (const float4*)x;
    int r = tid & 63, qg = tid >> 6;
    float* buf = hs + EHSBUF;  // buffer 1
    float4* b4 = (float4*)buf;
#pragma unroll
    for (int u = 0; u < 4; u++)
        b4[r * 17 + qg * 4 + u] = x4[(size_t)r * 8192 + qg * 4 + u];
    __syncthreads();
    chunk16(A, W + jl * WXE, buf + rh * EHSP, buf + (rh + 32) * EHSP);
}

// ================= role-split encoder =================
__global__ void __launch_bounds__(ETHR, 1) enc_ab_kernel(
    const float* __restrict__ in_seq,
    const float4* __restrict__ pW0x, const float4* __restrict__ pW0h,
    const float4* __restrict__ pW1x, const float4* __restrict__ pW1h,
    const float4* __restrict__ pb0, const float4* __restrict__ pb1,
    const float* __restrict__ zerobuf,
    float* __restrict__ y0, float* __restrict__ h1A, float* __restrict__ h1B,
    float* __restrict__ c0out, float* __restrict__ c1out)
{
    extern __shared__ __align__(16) unsigned char smraw[];
    int tid = threadIdx.x, jl = tid & 7, rh = tid >> 3;   // rh 0..31

    if (blockIdx.x < 64) {
        // ---------------- Group A: encoder layer 0 ----------------
        ulonglong2* Wh = (ulonglong2*)smraw;               // 8 x WSSE
        ulonglong2* Wx = Wh + 8 * WSSE;                    // 8 x WXE
        float* hs = (float*)(Wx + 8 * WXE);
        int j0 = blockIdx.x * 8, j = j0 + jl;
        int idx0 = (rh << 9) + j, idx1 = ((rh + 32) << 9) + j;

        {
            const ulonglong2* gh = (const ulonglong2*)pW0h + (size_t)j0 * HH;
#pragma unroll 2
            for (int i = tid; i < 8 * HH; i += ETHR) {
                int jj = i >> 9, kk = i & 511;
                Wh[jj * WSSE + kk] = gh[i];
            }
            const ulonglong2* gx = (const ulonglong2*)pW0x + (size_t)j0 * FF;
#pragma unroll
            for (int i = tid; i < 8 * FF; i += ETHR) {
                int jj = i >> 6, kk = i & 63;
                Wx[jj * WXE + kk] = gx[i];
            }
        }
        float4 b0 = pb0[j];
        float c0a = 0.f, c0b = 0.f;
        __syncthreads();

        for (int s = 0; s < TT; s++) {
            u64 A[8];
            bias_init(A, b0);
            // x projection first: independent of y0 -> hides the A-barrier wait
            ephase64(A, in_seq + (size_t)s * FF, Wx, hs, tid, jl, rh);
            if (s > 0) {
                // wait: all A blocks wrote y0[s-1]
                if (blockIdx.x == 0) {
                    if (tid > 0 && tid < 64) {
                        while (ld_acq(&g_flagA[tid * 8]) < (unsigned)s) { }
                    }
                    __syncthreads();
                    if (tid == 0) { __threadfence(); st_rel(&g_genA, (unsigned)s); }
                } else {
                    if (tid == 0) { while (ld_acq(&g_genA) < (unsigned)s) { } }
                    __syncthreads();
                }
            }
            const float* yp = (s == 0) ? zerobuf : (y0 + (size_t)(s - 1) * BH);
            ephase512(A, yp, Wh, hs, tid, jl, rh);
            float* yo = y0 + (size_t)s * BH;
            yo[idx0] = cellfin4(A[0], A[1], A[2], A[3], c0a);
            yo[idx1] = cellfin4(A[4], A[5], A[6], A[7], c0b);
            __syncthreads();
            if (tid == 0 && blockIdx.x > 0) {
                __threadfence();
                st_rel(&g_flagA[blockIdx.x * 8], (unsigned)(s + 1));
            }
        }
        // publish final watermark (genA = 512)
        if (blockIdx.x == 0) {
            if (tid > 0 && tid < 64) {
                while (ld_acq(&g_flagA[tid * 8]) < (unsigned)TT) { }
            }
            __syncthreads();
            if (tid == 0) { __threadfence(); st_rel(&g_genA, (unsigned)TT); }
        }
        c0out[idx0] = c0a; c0out[idx1] = c0b;
    } else {
        // ---------------- Group B: encoder layer 1 ----------------
        ulonglong2* Wx1 = (ulonglong2*)smraw;              // 8 x WSSE
        ulonglong2* Wh1 = Wx1 + 8 * WSSE;                  // 8 x WSSE
        float* hs = (float*)(Wh1 + 8 * WSSE);
        int bloc = blockIdx.x - 64;
        int j0 = bloc * 8, j = j0 + jl;
        int idx0 = (rh << 9) + j, idx1 = ((rh + 32) << 9) + j;

        {
            const ulonglong2* gx = (const ulonglong2*)pW1x + (size_t)j0 * HH;
            const ulonglong2* gh = (const ulonglong2*)pW1h + (size_t)j0 * HH;
#pragma unroll 2
            for (int i = tid; i < 8 * HH; i += ETHR) {
                int jj = i >> 9, kk = i & 511;
                Wx1[jj * WSSE + kk] = gx[i];
                Wh1[jj * WSSE + kk] = gh[i];
            }
        }
        float4 b1 = pb1[j];
        float c1a = 0.f, c1b = 0.f;
        __syncthreads();

        for (int t = 0; t < TT; t++) {
            // wait for y0[t] (watermark from A)
            if (tid == 0) { while (ld_acq(&g_genA) < (unsigned)(t + 1)) { } }
            __syncthreads();

            u64 A[8];
            bias_init(A, b1);
            ephase512(A, y0 + (size_t)t * BH, Wx1, hs, tid, jl, rh);

            if (t > 0) {
                // wait: all B blocks wrote h1[t-1] (mostly hidden behind x-phase)
                if (bloc == 0) {
                    if (tid > 0 && tid < 64) {
                        while (ld_acq(&g_flagB[tid * 8]) < (unsigned)t) { }
                    }
                    __syncthreads();
                    if (tid == 0) { __threadfence(); st_rel(&g_genB, (unsigned)t); }
                } else {
                    if (tid == 0) { while (ld_acq(&g_genB) < (unsigned)t) { } }
                    __syncthreads();
                }
            }
            const float* hp = (t == 0) ? zerobuf : (((t - 1) & 1) ? h1B : h1A);
            ephase512(A, hp, Wh1, hs, tid, jl, rh);
            float* ho = (t & 1) ? h1B : h1A;
            ho[idx0] = cellfin4(A[0], A[1], A[2], A[3], c1a);
            ho[idx1] = cellfin4(A[4], A[5], A[6], A[7], c1b);
            __syncthreads();
            if (tid == 0 && bloc > 0) {
                __threadfence();
                st_rel(&g_flagB[bloc * 8], (unsigned)(t + 1));
            }
        }
        c1out[idx0] = c1a; c1out[idx1] = c1b;
        // final h1 at t=511 (odd) -> h1B
    }
}

// ================= decoder (v5 verbatim: 128 blocks x 128 thr, 4 j) =================
__device__ __forceinline__ void grid_barrier(unsigned gen) {
    __syncthreads();
    int tid = threadIdx.x;
    if (blockIdx.x == 0) {
        if (tid > 0 && tid < DNBLK) {
            while (ld_acq(&g_flag[tid * 8]) < gen) { }
        }
        __syncthreads();
        if (tid == 0) st_rel(&g_bgen, gen);
    } else {
        if (tid == 0) {
            st_rel(&g_flag[blockIdx.x * 8], gen);
            while (ld_acq(&g_bgen) < gen) { }
        }
        __syncthreads();
    }
}

__device__ __forceinline__ void dphase512(
    u64* __restrict__ A, const float* __restrict__ x,
    const ulonglong2* __restrict__ W, float* hs, int tid, int jl, int rh)
{
    const float4* x4 = (const float4*)x;
    int rbase = tid >> 4, c4 = tid & 15;
    float4 pf[8];
#pragma unroll
    for (int u = 0; u < 8; u++) pf[u] = x4[(rbase + u * 8) * 128 + c4];
#pragma unroll 1
    for (int kc = 0; kc < HH; kc += 64) {
        float* buf = hs + ((kc >> 6) & 1) * DHSBUF;
        float4* buf4 = (float4*)buf;
#pragma unroll
        for (int u = 0; u < 8; u++) buf4[(rbase + u * 8) * 17 + c4] = pf[u];
        __syncthreads();
        if (kc + 64 < HH) {
            int k4 = (kc + 64) >> 2;
#pragma unroll
            for (int u = 0; u < 8; u++) pf[u] = x4[(rbase + u * 8) * 128 + k4 + c4];
        }
        chunk16(A, W + jl * DWSS + kc, buf + rh * DHSP, buf + (rh + 32) * DHSP);
    }
}
__device__ __forceinline__ void dphase64(
    u64* __restrict__ A, const float* __restrict__ x, long xstride,
    const ulonglong2* __restrict__ W, float* hs, int tid, int jl, int rh)
{
    const float4* x4 = (const float4*)x;
    long xs4 = xstride >> 2;
    int rbase = tid >> 4, c4 = tid & 15;
    float* buf = hs + DHSBUF;
    float4* buf4 = (float4*)buf;
#pragma unroll
    for (int u = 0; u < 8; u++)
        buf4[(rbase + u * 8) * 17 + c4] = x4[(long)(rbase + u * 8) * xs4 + c4];
    __syncthreads();
    chunk16(A, W + jl * DWSS64, buf + rh * DHSP, buf + (rh + 32) * DHSP);
}

__global__ void __launch_bounds__(DTHR, 1) dec_kernel(
    const float* __restrict__ in_seq,
    const float4* __restrict__ pWd0x, const float4* __restrict__ pWd0c,
    const float4* __restrict__ pWdh0, const float4* __restrict__ pWdx1,
    const float4* __restrict__ pWdh1,
    const float4* __restrict__ pbD0, const float4* __restrict__ pbD0c,
    const float4* __restrict__ pbD1,
    const float* __restrict__ h0init, const float* __restrict__ h1init,
    const float* __restrict__ c0in, const float* __restrict__ c1in,
    float* __restrict__ h0A, float* __restrict__ h0B, float* __restrict__ h1hist)
{
    extern __shared__ __align__(16) unsigned char smraw[];
    ulonglong2* Wc  = (ulonglong2*)smraw;
    ulonglong2* Wh0 = Wc  + 4 * DWSS;
    ulonglong2* Wx1 = Wh0 + 4 * DWSS;
    ulonglong2* Wh1 = Wx1 + 4 * DWSS;
    ulonglong2* W0x = Wh1 + 4 * DWSS;
    float* hs = (float*)(W0x + 4 * DWSS64);

    int tid = threadIdx.x, jl = tid & 3, rh = tid >> 2;
    int j0 = blockIdx.x * 4, j = j0 + jl;
    int idx0 = (rh << 9) + j;
    int idx1 = ((rh + 32) << 9) + j;

    {
        const ulonglong2* gc  = (const ulonglong2*)pWd0c + (size_t)j0 * HH;
        const ulonglong2* gh0 = (const ulonglong2*)pWdh0 + (size_t)j0 * HH;
        const ulonglong2* gx1 = (const ulonglong2*)pWdx1 + (size_t)j0 * HH;
        const ulonglong2* gh1 = (const ulonglong2*)pWdh1 + (size_t)j0 * HH;
#pragma unroll 2
        for (int i = tid; i < 4 * HH; i += DTHR) {
            int jj = i >> 9, kk = i & 511;
            Wc[jj * DWSS + kk]  = gc[i];
            Wh0[jj * DWSS + kk] = gh0[i];
            Wx1[jj * DWSS + kk] = gx1[i];
            Wh1[jj * DWSS + kk] = gh1[i];
        }
        const ulonglong2* g0x = (const ulonglong2*)pWd0x + (size_t)j0 * FF;
#pragma unroll
        for (int i = tid; i < 4 * FF; i += DTHR) {
            int jj = i >> 6, kk = i & 63;
            W0x[jj * DWSS64 + kk] = g0x[i];
        }
    }
    float4 bd0 = pbD0[j], bd0c = pbD0c[j], bd1 = pbD1[j];
    float c0a = c0in[idx0], c0b = c0in[idx1];
    float c1a = c1in[idx0], c1b = c1in[idx1];
    __syncthreads();

    unsigned gen = 0;
    const float* h0prev = h0init;
    const float* h1prev = h1init;

    for (int t = 0; t < FUT; t++) {
        u64 A[8];
        if (t == 0) {
            bias_init(A, bd0);
            dphase64(A, in_seq + (size_t)(TT - 1) * FF, (long)TT * FF, W0x, hs, tid, jl, rh);
        } else {
            bias_init(A, bd0c);
            dphase512(A, h1hist + (size_t)(t - 1) * BH, Wc, hs, tid, jl, rh);
        }
        dphase512(A, h0prev, Wh0, hs, tid, jl, rh);
        float* h0out = (t & 1) ? h0B : h0A;
        h0out[idx0] = cellfin4(A[0], A[1], A[2], A[3], c0a);
        h0out[idx1] = cellfin4(A[4], A[5], A[6], A[7], c0b);
        gen++; grid_barrier(gen);

        u64 R[8];
        bias_init(R, bd1);
        dphase512(R, h0out, Wx1, hs, tid, jl, rh);
        dphase512(R, h1prev, Wh1, hs, tid, jl, rh);
        float* h1o = h1hist + (size_t)t * BH;
        h1o[idx0] = cellfin4(R[0], R[1], R[2], R[3], c1a);
        h1o[idx1] = cellfin4(R[4], R[5], R[6], R[7], c1b);
        if (t < FUT - 1) { gen++; grid_barrier(gen); }
        h0prev = h0out;
        h1prev = h1o;
    }
}

// ---------------- setup kernels ----------------
__global__ void pack_all_kernel(
    const float* __restrict__ s0, const float* __restrict__ s1,
    const float* __restrict__ s2, const float* __restrict__ s3,
    const float* __restrict__ s4, const float* __restrict__ s5,
    const float* __restrict__ s6, const float* __restrict__ s7,
    float4* __restrict__ d0, float4* __restrict__ d1,
    float4* __restrict__ d2, float4* __restrict__ d3,
    float4* __restrict__ d4, float4* __restrict__ d5,
    float4* __restrict__ d6, float4* __restrict__ d7,
    const float* __restrict__ bi0, const float* __restrict__ bh0,
    const float* __restrict__ bi1, const float* __restrict__ bh1,
    const float* __restrict__ bi2, const float* __restrict__ bh2,
    const float* __restrict__ bi3, const float* __restrict__ bh3,
    float4* __restrict__ pb0, float4* __restrict__ pb1,
    float4* __restrict__ pb2, float4* __restrict__ pb3)
{
    int m = blockIdx.y;
    int idx = blockIdx.x * 256 + threadIdx.x;
    if (m < 8) {
        const float* S; float4* D; int Kin;
        switch (m) {
            case 0: S = s0; D = d0; Kin = FF; break;
            case 1: S = s1; D = d1; Kin = HH; break;
            case 2: S = s2; D = d2; Kin = HH; break;
            case 3: S = s3; D = d3; Kin = HH; break;
            case 4: S = s4; D = d4; Kin = FF; break;
            case 5: S = s5; D = d5; Kin = HH; break;
            case 6: S = s6; D = d6; Kin = HH; break;
            default: S = s7; D = d7; Kin = HH; break;
        }
        int K2 = Kin >> 1;
        if (idx >= HH * K2) return;
        int jj = idx / K2, k2 = idx - jj * K2;
        int k = k2 * 2;
        D[idx * 2 + 0] = make_float4(S[jj * Kin + k], S[jj * Kin + k + 1],
                                     S[(jj + 512) * Kin + k], S[(jj + 512) * Kin + k + 1]);
        D[idx * 2 + 1] = make_float4(S[(jj + 1024) * Kin + k], S[(jj + 1024) * Kin + k + 1],
                                     S[(jj + 1536) * Kin + k], S[(jj + 1536) * Kin + k + 1]);
    } else {
        if (idx >= 4 * HH) return;
        int which = idx >> 9, jj = idx & 511;
        const float* A; const float* Bb; float4* P;
        switch (which) {
            case 0: A = bi0; Bb = bh0; P = pb0; break;
            case 1: A = bi1; Bb = bh1; P = pb1; break;
            case 2: A = bi2; Bb = bh2; P = pb2; break;
            default: A = bi3; Bb = bh3; P = pb3; break;
        }
        P[jj] = make_float4(A[jj] + Bb[jj], A[jj + 512] + Bb[jj + 512],
                            A[jj + 1024] + Bb[jj + 1024], A[jj + 1536] + Bb[jj + 1536]);
    }
}

__global__ void combine_dec0_kernel(
    const float* __restrict__ dWih0, const float* __restrict__ fcW,
    const float* __restrict__ dbih0, const float* __restrict__ dbhh0,
    const float* __restrict__ fcb,
    float4* __restrict__ Pc, float4* __restrict__ pbc)
{
    int idx = blockIdx.x * 256 + threadIdx.x;
    if (idx >= HH * 256) return;
    int jj = idx >> 8, h = (idx & 255) * 2;
    float si0 = 0, si1 = 0, sf0 = 0, sf1 = 0, sg0 = 0, sg1 = 0, so0 = 0, so1 = 0;
#pragma unroll 4
    for (int n = 0; n < FF; n++) {
        float f0 = fcW[n * HH + h], f1 = fcW[n * HH + h + 1];
        float wi = dWih0[jj * FF + n];
        float wf = dWih0[(jj + 512) * FF + n];
        float wg = dWih0[(jj + 1024) * FF + n];
        float wo = dWih0[(jj + 1536) * FF + n];
        si0 += wi * f0; si1 += wi * f1;
        sf0 += wf * f0; sf1 += wf * f1;
        sg0 += wg * f0; sg1 += wg * f1;
        so0 += wo * f0; so1 += wo * f1;
    }
    Pc[idx * 2 + 0] = make_float4(si0, si1, sf0, sf1);
    Pc[idx * 2 + 1] = make_float4(sg0, sg1, so0, so1);
    if ((idx & 255) == 0) {
        float bi = dbih0[jj] + dbhh0[jj];
        float bf = dbih0[jj + 512] + dbhh0[jj + 512];
        float bg = dbih0[jj + 1024] + dbhh0[jj + 1024];
        float bo = dbih0[jj + 1536] + dbhh0[jj + 1536];
#pragma unroll 4
        for (int n = 0; n < FF; n++) {
            float f = fcb[n];
            bi += dWih0[jj * FF + n] * f;
            bf += dWih0[(jj + 512) * FF + n] * f;
            bg += dWih0[(jj + 1024) * FF + n] * f;
            bo += dWih0[(jj + 1536) * FF + n] * f;
        }
        pbc[jj] = make_float4(bi, bf, bg, bo);
    }
}

__global__ void init_kernel(float* zerobuf) {
    int i = blockIdx.x * 256 + threadIdx.x;
    if (i < BH) zerobuf[i] = 0.f;
    if (i < DNBLK * 8) g_flag[i] = 0;
    if (i < 64 * 8) { g_flagA[i] = 0; g_flagB[i] = 0; }
    if (i == 0) { g_bgen = 0; g_genA = 0; g_genB = 0; }
}
__global__ void reset_bar_kernel() {
    int i = threadIdx.x;
    if (i < DNBLK * 8) g_flag[i] = 0;
    if (i == 0) g_bgen = 0;
}

__global__ void final_fc_kernel(const float* __restrict__ h1hist, const float* __restrict__ fcW,
                                const float* __restrict__ fcb, float* __restrict__ out) {
    int t = blockIdx.y;
    int lx = blockIdx.x * 256 + threadIdx.x;
    int b = lx >> 6, n = lx & 63;
    const float4* h4 = (const float4*)(h1hist + ((size_t)t * BB + b) * HH);
    const float4* w4 = (const float4*)(fcW + (size_t)n * HH);
    float acc = fcb[n];
#pragma unroll 8
    for (int k = 0; k < HH / 4; k++) {
        float4 a = h4[k], ww = w4[k];
        acc += a.x * ww.x + a.y * ww.y + a.z * ww.z + a.w * ww.w;
    }
    out[((size_t)b * FUT + t) * FF + n] = acc;
}

// ---------------- host ----------------
extern "C" void kernel_launch(void* const* d_in, const int* in_sizes, int n_in,
                              void* d_out, int out_size) {
    const float* in_seq = (const float*)d_in[0];
    const float* eWih0  = (const float*)d_in[1];
    const float* eWhh0  = (const float*)d_in[2];
    const float* ebih0  = (const float*)d_in[3];
    const float* ebhh0  = (const float*)d_in[4];
    const float* eWih1  = (const float*)d_in[5];
    const float* eWhh1  = (const float*)d_in[6];
    const float* ebih1  = (const float*)d_in[7];
    const float* ebhh1  = (const float*)d_in[8];
    const float* dWih0  = (const float*)d_in[9];
    const float* dWhh0  = (const float*)d_in[10];
    const float* dbih0  = (const float*)d_in[11];
    const float* dbhh0  = (const float*)d_in[12];
    const float* dWih1  = (const float*)d_in[13];
    const float* dWhh1  = (const float*)d_in[14];
    const float* dbih1  = (const float*)d_in[15];
    const float* dbhh1  = (const float*)d_in[16];
    const float* fcW    = (const float*)d_in[17];
    const float* fcb    = (const float*)d_in[18];
    float* out = (float*)d_out;

    static int s_attr_done = 0;
    if (!s_attr_done) {
        cudaFuncSetAttribute(enc_ab_kernel, cudaFuncAttributeMaxDynamicSharedMemorySize, ENC_SMEM);
        cudaFuncSetAttribute(dec_kernel, cudaFuncAttributeMaxDynamicSharedMemorySize, DEC_SMEM);
        s_attr_done = 1;
    }

    float4 *pWeih0, *pWehh0, *pWeih1, *pWehh1, *pWdih0, *pWdhh0, *pWdih1, *pWdhh1, *pWd0c;
    float4 *pbE0, *pbE1, *pbD0, *pbD1, *pbD0c;
    float *y0, *h1hist, *zerobuf, *c0, *c1, *h1A, *h1B, *h0A, *h0B;
    cudaGetSymbolAddress((void**)&y0,      g_y0);
    cudaGetSymbolAddress((void**)&h1hist,  g_h1hist);
    cudaGetSymbolAddress((void**)&zerobuf, g_zero);
    cudaGetSymbolAddress((void**)&c0,      g_c0);
    cudaGetSymbolAddress((void**)&c1,      g_c1);
    cudaGetSymbolAddress((void**)&h1A,     g_h1A);
    cudaGetSymbolAddress((void**)&h1B,     g_h1B);
    cudaGetSymbolAddress((void**)&h0A,     g_h0A);
    cudaGetSymbolAddress((void**)&h0B,     g_h0B);
    cudaGetSymbolAddress((void**)&pWeih0,  g_pW_enc_ih0);
    cudaGetSymbolAddress((void**)&pWehh0,  g_pW_enc_hh0);
    cudaGetSymbolAddress((void**)&pWeih1,  g_pW_enc_ih1);
    cudaGetSymbolAddress((void**)&pWehh1,  g_pW_enc_hh1);
    cudaGetSymbolAddress((void**)&pWdih0,  g_pW_dec_ih0);
    cudaGetSymbolAddress((void**)&pWdhh0,  g_pW_dec_hh0);
    cudaGetSymbolAddress((void**)&pWdih1,  g_pW_dec_ih1);
    cudaGetSymbolAddress((void**)&pWdhh1,  g_pW_dec_hh1);
    cudaGetSymbolAddress((void**)&pWd0c,   g_pW_dec0c);
    cudaGetSymbolAddress((void**)&pbE0,    g_pb_enc0);
    cudaGetSymbolAddress((void**)&pbE1,    g_pb_enc1);
    cudaGetSymbolAddress((void**)&pbD0,    g_pb_dec0);
    cudaGetSymbolAddress((void**)&pbD1,    g_pb_dec1);
    cudaGetSymbolAddress((void**)&pbD0c,   g_pb_dec0c);

    // Launch order: 2 harness pre-launches + [pack, combine, init, enc] -> enc at idx 5.
    {
        dim3 grid(512, 9);
        pack_all_kernel<<<grid, 256>>>(
            eWih0, eWhh0, eWih1, eWhh1, dWih0, dWhh0, dWih1, dWhh1,
            pWeih0, pWehh0, pWeih1, pWehh1, pWdih0, pWdhh0, pWdih1, pWdhh1,
            ebih0, ebhh0, ebih1, ebhh1, dbih0, dbhh0, dbih1, dbhh1,
            pbE0, pbE1, pbD0, pbD1);
    }
    combine_dec0_kernel<<<(HH * 256 + 255) / 256, 256>>>(
        dWih0, fcW, dbih0, dbhh0, fcb, pWd0c, pbD0c);
    init_kernel<<<(BH + 255) / 256, 256>>>(zerobuf);

    enc_ab_kernel<<<128, ETHR, ENC_SMEM>>>(
        in_seq, pWeih0, pWehh0, pWeih1, pWehh1, pbE0, pbE1,
        zerobuf, y0, h1A, h1B, c0, c1);

    reset_bar_kernel<<<1, 1024>>>();

    dec_kernel<<<DNBLK, DTHR, DEC_SMEM>>>(
        in_seq, pWdih0, pWd0c, pWdhh0, pWdih1, pWdhh1,
        pbD0, pbD0c, pbD1,
        y0 + (size_t)(TT - 1) * BH,   // enc L0 final h
        h1B,                           // enc L1 final h (t=511 odd -> h1B)
        c0, c1, h0A, h0B, h1hist);

    {
        dim3 grid(16, FUT);
        final_fc_kernel<<<grid, 256>>>(h1hist, fcW, fcb, out);
    }
}

// round 16
// speedup vs baseline: 1.0900x; 1.0900x over previous
#include <cuda_runtime.h>

// LSTM seq2seq: B=64, T=512, F=64, H=512, FUT=96 — persistent v10.
// v5 structure (best: 14559us) with one change: warp-per-j mapping so weight
// LDS.128 are single-address broadcasts (1 wavefront, was 4) and activations
// staged transposed (k2-pair, row) so act loads are contiguous 512B.
// Cuts the binding L1TEX wavefront count ~2x.

#define BB 64
#define TT 512
#define FF 64
#define HH 512
#define FUT 96
#define BH (BB*HH)          // 32768

#define NBLK 128
#define NTHR 128
#define WSS   514           // u2 per j row (K=512)
#define WSS64 66            // u2 per j row (K=64)
#define ACTU 2048           // u64 per act buffer: 16 p x 128 (=(k2pair,row) pairs)

typedef unsigned long long u64;

// ---------------- device scratch ----------------
__device__ float  g_y0[TT*BB*HH];
__device__ float  g_h1hist[FUT*BB*HH];
__device__ float  g_zero[BH];
__device__ float  g_c0[BH], g_c1[BH];
__device__ float  g_h1A[BH], g_h1B[BH], g_h0A[BH], g_h0B[BH];

// pair-packed weights: per (j,k2): float4 {i(k),i(k+1),f(k),f(k+1)}, {g..,o..}
__device__ float4 g_pW_enc_ih0[HH*FF];
__device__ float4 g_pW_enc_hh0[HH*HH];
__device__ float4 g_pW_enc_ih1[HH*HH];
__device__ float4 g_pW_enc_hh1[HH*HH];
__device__ float4 g_pW_dec_ih0[HH*FF];
__device__ float4 g_pW_dec_hh0[HH*HH];
__device__ float4 g_pW_dec_ih1[HH*HH];
__device__ float4 g_pW_dec_hh1[HH*HH];
__device__ float4 g_pW_dec0c[HH*HH];
__device__ float4 g_pb_enc0[HH], g_pb_enc1[HH], g_pb_dec0[HH], g_pb_dec1[HH], g_pb_dec0c[HH];

__device__ unsigned g_bgen;
__device__ unsigned g_flag[NBLK*8];

// ---------------- f32x2 helpers ----------------
__device__ __forceinline__ u64 pack2(float a, float b) {
    u64 r;
    asm("mov.b64 %0, {%1, %2};" : "=l"(r) : "r"(__float_as_uint(a)), "r"(__float_as_uint(b)));
    return r;
}
__device__ __forceinline__ float2 unpack2(u64 v) {
    unsigned int lo, hi;
    asm("mov.b64 {%0, %1}, %2;" : "=r"(lo), "=r"(hi) : "l"(v));
    return make_float2(__uint_as_float(lo), __uint_as_float(hi));
}
__device__ __forceinline__ void ffma2(u64& d, u64 a, u64 b) {
    asm("fma.rn.f32x2 %0, %1, %2, %0;" : "+l"(d) : "l"(a), "l"(b));
}

// ---------------- flag-tree grid barrier (v5) ----------------
__device__ __forceinline__ void grid_barrier(unsigned gen) {
    __syncthreads();
    int tid = threadIdx.x;
    if (blockIdx.x == 0) {
        if (tid > 0 && tid < NBLK) {
            unsigned v;
            do {
                asm volatile("ld.acquire.gpu.u32 %0, [%1];" : "=r"(v) : "l"(&g_flag[tid * 8]));
            } while (v < gen);
        }
        __syncthreads();
        if (tid == 0) {
            asm volatile("st.release.gpu.u32 [%0], %1;" :: "l"(&g_bgen), "r"(gen));
        }
    } else {
        if (tid == 0) {
            asm volatile("st.release.gpu.u32 [%0], %1;" :: "l"(&g_flag[blockIdx.x * 8]), "r"(gen));
            unsigned v;
            do {
                asm volatile("ld.acquire.gpu.u32 %0, [%1];" : "=r"(v) : "l"(&g_bgen));
            } while (v < gen);
        }
        __syncthreads();
    }
}

// ---------------- chunk compute: warp = one j, lane l = rows l & l+32 ----------------
// act layout per chunk: u64 buf[16][128]: entry p (k2 pair 2p,2p+1) x (row r: [2r]=k2 even,[2r+1]=odd).
// A[0..3]: row l gates i,f,g,o (u64 = 2 k-lanes); A[4..7]: row l+32.
// Weights: all lanes read the SAME address -> broadcast (1 wavefront).
__device__ __forceinline__ void chunkN(
    u64* __restrict__ A, const ulonglong2* __restrict__ w,
    const u64* __restrict__ act, int l)
{
#pragma unroll
    for (int p = 0; p < 16; p++) {
        ulonglong2 a = *(const ulonglong2*)(act + p * 128 + 2 * l);        // row l
        ulonglong2 b = *(const ulonglong2*)(act + p * 128 + 64 + 2 * l);   // row l+32
        ulonglong2 wif0 = w[4 * p + 0], wgo0 = w[4 * p + 1];
        ulonglong2 wif1 = w[4 * p + 2], wgo1 = w[4 * p + 3];
        ffma2(A[0], a.x, wif0.x); ffma2(A[1], a.x, wif0.y);
        ffma2(A[2], a.x, wgo0.x); ffma2(A[3], a.x, wgo0.y);
        ffma2(A[4], b.x, wif0.x); ffma2(A[5], b.x, wif0.y);
        ffma2(A[6], b.x, wgo0.x); ffma2(A[7], b.x, wgo0.y);
        ffma2(A[0], a.y, wif1.x); ffma2(A[1], a.y, wif1.y);
        ffma2(A[2], a.y, wgo1.x); ffma2(A[3], a.y, wgo1.y);
        ffma2(A[4], b.y, wif1.x); ffma2(A[5], b.y, wif1.y);
        ffma2(A[6], b.y, wgo1.x); ffma2(A[7], b.y, wgo1.y);
    }
}
// Dual: two weight matrices sharing the same activations.
__device__ __forceinline__ void chunkD(
    u64* __restrict__ A, u64* __restrict__ B,
    const ulonglong2* __restrict__ wa, const ulonglong2* __restrict__ wb,
    const u64* __restrict__ act, int l)
{
#pragma unroll
    for (int p = 0; p < 16; p++) {
        ulonglong2 a = *(const ulonglong2*)(act + p * 128 + 2 * l);
        ulonglong2 b = *(const ulonglong2*)(act + p * 128 + 64 + 2 * l);
        ulonglong2 waif0 = wa[4 * p + 0], wago0 = wa[4 * p + 1];
        ulonglong2 waif1 = wa[4 * p + 2], wago1 = wa[4 * p + 3];
        ulonglong2 wbif0 = wb[4 * p + 0], wbgo0 = wb[4 * p + 1];
        ulonglong2 wbif1 = wb[4 * p + 2], wbgo1 = wb[4 * p + 3];
        ffma2(A[0], a.x, waif0.x); ffma2(A[1], a.x, waif0.y);
        ffma2(A[2], a.x, wago0.x); ffma2(A[3], a.x, wago0.y);
        ffma2(A[4], b.x, waif0.x); ffma2(A[5], b.x, waif0.y);
        ffma2(A[6], b.x, wago0.x); ffma2(A[7], b.x, wago0.y);
        ffma2(B[0], a.x, wbif0.x); ffma2(B[1], a.x, wbif0.y);
        ffma2(B[2], a.x, wbgo0.x); ffma2(B[3], a.x, wbgo0.y);
        ffma2(B[4], b.x, wbif0.x); ffma2(B[5], b.x, wbif0.y);
        ffma2(B[6], b.x, wbgo0.x); ffma2(B[7], b.x, wbgo0.y);
        ffma2(A[0], a.y, waif1.x); ffma2(A[1], a.y, waif1.y);
        ffma2(A[2], a.y, wago1.x); ffma2(A[3], a.y, wago1.y);
        ffma2(A[4], b.y, waif1.x); ffma2(A[5], b.y, waif1.y);
        ffma2(A[6], b.y, wago1.x); ffma2(A[7], b.y, wago1.y);
        ffma2(B[0], a.y, wbif1.x); ffma2(B[1], a.y, wbif1.y);
        ffma2(B[2], a.y, wbgo1.x); ffma2(B[3], a.y, wbgo1.y);
        ffma2(B[4], b.y, wbif1.x); ffma2(B[5], b.y, wbif1.y);
        ffma2(B[6], b.y, wbgo1.x); ffma2(B[7], b.y, wbgo1.y);
    }
}

// ---------------- staged K=512 phases (x: [64 rows][xs4 float4]) ----------------
// Staging: thread (r = tid&63, qg = tid>>6) reads 8 float4 of row r, writes
// transposed pairs: buf[(qg*8+u)*128 + 2r] = {pack2(x,y), pack2(z,w)}.
template <bool DUAL>
__device__ __forceinline__ void phase512(
    u64* __restrict__ A, u64* __restrict__ B,
    const float* __restrict__ x, int xs4,
    const ulonglong2* __restrict__ Wa, const ulonglong2* __restrict__ Wb,
    u64* __restrict__ act, int tid, int wid, int l)
{
    const float4* x4 = (const float4*)x;
    int r = tid & 63, qg = tid >> 6;
    const float4* xr = x4 + (size_t)r * xs4 + qg * 8;
    float4 pf[8];
#pragma unroll
    for (int u = 0; u < 8; u++) pf[u] = xr[u];
#pragma unroll 1
    for (int c = 0; c < 8; c++) {
        u64* buf = act + (c & 1) * ACTU;
#pragma unroll
        for (int u = 0; u < 8; u++) {
            ulonglong2 v;
            v.x = pack2(pf[u].x, pf[u].y);
            v.y = pack2(pf[u].z, pf[u].w);
            *(ulonglong2*)(buf + (qg * 8 + u) * 128 + 2 * r) = v;
        }
        __syncthreads();
        if (c < 7) {
#pragma unroll
            for (int u = 0; u < 8; u++) pf[u] = xr[(c + 1) * 16 + u];
        }
        if (DUAL) chunkD(A, B, Wa + wid * WSS + c * 64, Wb + wid * WSS + c * 64, buf, l);
        else      chunkN(A, Wa + wid * WSS + c * 64, buf, l);
    }
}

// K=64 phase (one chunk); uses act buffer 1 (parity-safe vs phase512 start).
__device__ __forceinline__ void phase64(
    u64* __restrict__ A, const float* __restrict__ x, int xs4,
    const ulonglong2* __restrict__ W, u64* __restrict__ act,
    int tid, int wid, int l)
{
    const float4* x4 = (const float4*)x;
    int r = tid & 63, qg = tid >> 6;
    const float4* xr = x4 + (size_t)r * xs4 + qg * 8;
    u64* buf = act + ACTU;
#pragma unroll
    for (int u = 0; u < 8; u++) {
        float4 v = xr[u];
        ulonglong2 t;
        t.x = pack2(v.x, v.y);
        t.y = pack2(v.z, v.w);
        *(ulonglong2*)(buf + (qg * 8 + u) * 128 + 2 * r) = t;
    }
    __syncthreads();
    chunkN(A, W + wid * WSS64, buf, l);
}

__device__ __forceinline__ float cellfin4(u64 gi2, u64 gf2, u64 gg2, u64 go2, float& c) {
    float2 vi = unpack2(gi2), vf = unpack2(gf2), vg = unpack2(gg2), vo = unpack2(go2);
    float gi = vi.x + vi.y, gf = vf.x + vf.y, gg = vg.x + vg.y, go = vo.x + vo.y;
    float si = 1.f / (1.f + __expf(-gi));
    float sf = 1.f / (1.f + __expf(-gf));
    float so = 1.f / (1.f + __expf(-go));
    float cn = sf * c + si * tanhf(gg);
    c = cn;
    return so * tanhf(cn);
}
__device__ __forceinline__ void bias_init(u64* A, float4 b) {
    A[0] = pack2(b.x, 0.f); A[1] = pack2(b.y, 0.f);
    A[2] = pack2(b.z, 0.f); A[3] = pack2(b.w, 0.f);
    A[4] = A[0]; A[5] = A[1]; A[6] = A[2]; A[7] = A[3];
}

#define ENC_SMEM ((3*4*WSS + 4*WSS64)*16 + 2*ACTU*8)   // 135680
#define DEC_SMEM ((4*4*WSS + 4*WSS64)*16 + 2*ACTU*8)   // 168576

// ---------------- persistent encoder: L0 + L1 software-pipelined (v5) ----------------
__global__ void __launch_bounds__(NTHR, 1) enc_kernel(
    const float* __restrict__ in_seq,
    const float4* __restrict__ pW0x, const float4* __restrict__ pW0h,
    const float4* __restrict__ pW1x, const float4* __restrict__ pW1h,
    const float4* __restrict__ pb0, const float4* __restrict__ pb1,
    const float* __restrict__ zerobuf,
    float* __restrict__ y0, float* __restrict__ h1A, float* __restrict__ h1B,
    float* __restrict__ c0out, float* __restrict__ c1out)
{
    extern __shared__ __align__(16) unsigned char smraw[];
    ulonglong2* W0h = (ulonglong2*)smraw;
    ulonglong2* W1x = W0h + 4 * WSS;
    ulonglong2* W1h = W1x + 4 * WSS;
    ulonglong2* W0x = W1h + 4 * WSS;
    u64* act = (u64*)(W0x + 4 * WSS64);

    int tid = threadIdx.x;
    int wid = tid >> 5, l = tid & 31;
    int j0 = blockIdx.x * 4, j = j0 + wid;
    int idx0 = (l << 9) + j;
    int idx1 = ((l + 32) << 9) + j;

    {   // load weight tiles (once)
        const ulonglong2* g0h = (const ulonglong2*)pW0h + (size_t)j0 * HH;
        const ulonglong2* g1x = (const ulonglong2*)pW1x + (size_t)j0 * HH;
        const ulonglong2* g1h = (const ulonglong2*)pW1h + (size_t)j0 * HH;
#pragma unroll 2
        for (int i = tid; i < 4 * HH; i += NTHR) {
            int jj = i >> 9, kk = i & 511;
            W0h[jj * WSS + kk] = g0h[i];
            W1x[jj * WSS + kk] = g1x[i];
            W1h[jj * WSS + kk] = g1h[i];
        }
        const ulonglong2* g0x = (const ulonglong2*)pW0x + (size_t)j0 * FF;
#pragma unroll
        for (int i = tid; i < 4 * FF; i += NTHR) {
            int jj = i >> 6, kk = i & 63;
            W0x[jj * WSS64 + kk] = g0x[i];
        }
    }
    float4 b0 = pb0[j], b1 = pb1[j];
    float c0a = 0.f, c0b = 0.f, c1a = 0.f, c1b = 0.f;
    __syncthreads();

    unsigned gen = 0;
    for (int slot = 0; slot <= TT; slot++) {
        bool doL0 = (slot < TT);
        bool doL1 = (slot > 0);
        const float* yprev = (slot == 0) ? zerobuf : (y0 + (size_t)(slot - 1) * BH);

        u64 A[8], B[8];
        if (doL0) {
            bias_init(A, b0);
            phase64(A, in_seq + (size_t)slot * FF, TT * FF / 4, W0x, act, tid, wid, l);
        }
        if (doL1) bias_init(B, b1);

        if (doL0 && doL1)
            phase512<true>(A, B, yprev, 128, W0h, W1x, act, tid, wid, l);
        else if (doL0)
            phase512<false>(A, A, yprev, 128, W0h, W0h, act, tid, wid, l);
        else
            phase512<false>(B, B, yprev, 128, W1x, W1x, act, tid, wid, l);

        if (doL1) {
            const float* h1p = (slot == 1) ? zerobuf : ((slot & 1) ? h1A : h1B);
            phase512<false>(B, B, h1p, 128, W1h, W1h, act, tid, wid, l);
            float* h1o = (slot & 1) ? h1B : h1A;
            h1o[idx0] = cellfin4(B[0], B[1], B[2], B[3], c1a);
            h1o[idx1] = cellfin4(B[4], B[5], B[6], B[7], c1b);
        }
        if (doL0) {
            float* yo = y0 + (size_t)slot * BH;
            yo[idx0] = cellfin4(A[0], A[1], A[2], A[3], c0a);
            yo[idx1] = cellfin4(A[4], A[5], A[6], A[7], c0b);
        }

        if (slot < TT) {
            gen++;
            grid_barrier(gen);
        }
    }
    c0out[idx0] = c0a; c0out[idx1] = c0b;
    c1out[idx0] = c1a; c1out[idx1] = c1b;
    // final h1 at slot TT (even) -> h1A
}

// ---------------- persistent decoder ----------------
__global__ void __launch_bounds__(NTHR, 1) dec_kernel(
    const float* __restrict__ in_seq,
    const float4* __restrict__ pWd0x, const float4* __restrict__ pWd0c,
    const float4* __restrict__ pWdh0, const float4* __restrict__ pWdx1,
    const float4* __restrict__ pWdh1,
    const float4* __restrict__ pbD0, const float4* __restrict__ pbD0c,
    const float4* __restrict__ pbD1,
    const float* __restrict__ h0init, const float* __restrict__ h1init,
    const float* __restrict__ c0in, const float* __restrict__ c1in,
    float* __restrict__ h0A, float* __restrict__ h0B, float* __restrict__ h1hist)
{
    extern __shared__ __align__(16) unsigned char smraw[];
    ulonglong2* Wc  = (ulonglong2*)smraw;
    ulonglong2* Wh0 = Wc  + 4 * WSS;
    ulonglong2* Wx1 = Wh0 + 4 * WSS;
    ulonglong2* Wh1 = Wx1 + 4 * WSS;
    ulonglong2* W0x = Wh1 + 4 * WSS;
    u64* act = (u64*)(W0x + 4 * WSS64);

    int tid = threadIdx.x;
    int wid = tid >> 5, l = tid & 31;
    int j0 = blockIdx.x * 4, j = j0 + wid;
    int idx0 = (l << 9) + j;
    int idx1 = ((l + 32) << 9) + j;

    {
        const ulonglong2* gc  = (const ulonglong2*)pWd0c + (size_t)j0 * HH;
        const ulonglong2* gh0 = (const ulonglong2*)pWdh0 + (size_t)j0 * HH;
        const ulonglong2* gx1 = (const ulonglong2*)pWdx1 + (size_t)j0 * HH;
        const ulonglong2* gh1 = (const ulonglong2*)pWdh1 + (size_t)j0 * HH;
#pragma unroll 2
        for (int i = tid; i < 4 * HH; i += NTHR) {
            int jj = i >> 9, kk = i & 511;
            Wc[jj * WSS + kk]  = gc[i];
            Wh0[jj * WSS + kk] = gh0[i];
            Wx1[jj * WSS + kk] = gx1[i];
            Wh1[jj * WSS + kk] = gh1[i];
        }
        const ulonglong2* g0x = (const ulonglong2*)pWd0x + (size_t)j0 * FF;
#pragma unroll
        for (int i = tid; i < 4 * FF; i += NTHR) {
            int jj = i >> 6, kk = i & 63;
            W0x[jj * WSS64 + kk] = g0x[i];
        }
    }
    float4 bd0 = pbD0[j], bd0c = pbD0c[j], bd1 = pbD1[j];
    float c0a = c0in[idx0], c0b = c0in[idx1];
    float c1a = c1in[idx0], c1b = c1in[idx1];
    __syncthreads();

    unsigned gen = 0;
    const float* h0prev = h0init;
    const float* h1prev = h1init;

    for (int t = 0; t < FUT; t++) {
        u64 A[8];
        if (t == 0) {
            bias_init(A, bd0);
            phase64(A, in_seq + (size_t)(TT - 1) * FF, TT * FF / 4, W0x, act, tid, wid, l);
        } else {
            bias_init(A, bd0c);
            phase512<false>(A, A, h1hist + (size_t)(t - 1) * BH, 128, Wc, Wc, act, tid, wid, l);
        }
        phase512<false>(A, A, h0prev, 128, Wh0, Wh0, act, tid, wid, l);
        float* h0out = (t & 1) ? h0B : h0A;
        h0out[idx0] = cellfin4(A[0], A[1], A[2], A[3], c0a);
        h0out[idx1] = cellfin4(A[4], A[5], A[6], A[7], c0b);
        gen++; grid_barrier(gen);

        u64 R[8];
        bias_init(R, bd1);
        phase512<false>(R, R, h0out, 128, Wx1, Wx1, act, tid, wid, l);
        phase512<false>(R, R, h1prev, 128, Wh1, Wh1, act, tid, wid, l);
        float* h1o = h1hist + (size_t)t * BH;
        h1o[idx0] = cellfin4(R[0], R[1], R[2], R[3], c1a);
        h1o[idx1] = cellfin4(R[4], R[5], R[6], R[7], c1b);
        if (t < FUT - 1) { gen++; grid_barrier(gen); }
        h0prev = h0out;
        h1prev = h1o;
    }
}

// ---------------- setup kernels (v5 verbatim; pair-packed format unchanged) ----------------
__global__ void pack_all_kernel(
    const float* __restrict__ s0, const float* __restrict__ s1,
    const float* __restrict__ s2, const float* __restrict__ s3,
    const float* __restrict__ s4, const float* __restrict__ s5,
    const float* __restrict__ s6, const float* __restrict__ s7,
    float4* __restrict__ d0, float4* __restrict__ d1,
    float4* __restrict__ d2, float4* __restrict__ d3,
    float4* __restrict__ d4, float4* __restrict__ d5,
    float4* __restrict__ d6, float4* __restrict__ d7,
    const float* __restrict__ bi0, const float* __restrict__ bh0,
    const float* __restrict__ bi1, const float* __restrict__ bh1,
    const float* __restrict__ bi2, const float* __restrict__ bh2,
    const float* __restrict__ bi3, const float* __restrict__ bh3,
    float4* __restrict__ pb0, float4* __restrict__ pb1,
    float4* __restrict__ pb2, float4* __restrict__ pb3)
{
    int m = blockIdx.y;
    int idx = blockIdx.x * 256 + threadIdx.x;
    if (m < 8) {
        const float* S; float4* D; int Kin;
        switch (m) {
            case 0: S = s0; D = d0; Kin = FF; break;
            case 1: S = s1; D = d1; Kin = HH; break;
            case 2: S = s2; D = d2; Kin = HH; break;
            case 3: S = s3; D = d3; Kin = HH; break;
            case 4: S = s4; D = d4; Kin = FF; break;
            case 5: S = s5; D = d5; Kin = HH; break;
            case 6: S = s6; D = d6; Kin = HH; break;
            default: S = s7; D = d7; Kin = HH; break;
        }
        int K2 = Kin >> 1;
        if (idx >= HH * K2) return;
        int jj = idx / K2, k2 = idx - jj * K2;
        int k = k2 * 2;
        D[idx * 2 + 0] = make_float4(S[jj * Kin + k], S[jj * Kin + k + 1],
                                     S[(jj + 512) * Kin + k], S[(jj + 512) * Kin + k + 1]);
        D[idx * 2 + 1] = make_float4(S[(jj + 1024) * Kin + k], S[(jj + 1024) * Kin + k + 1],
                                     S[(jj + 1536) * Kin + k], S[(jj + 1536) * Kin + k + 1]);
    } else {
        if (idx >= 4 * HH) return;
        int which = idx >> 9, jj = idx & 511;
        const float* A; const float* Bb; float4* P;
        switch (which) {
            case 0: A = bi0; Bb = bh0; P = pb0; break;
            case 1: A = bi1; Bb = bh1; P = pb1; break;
            case 2: A = bi2; Bb = bh2; P = pb2; break;
            default: A = bi3; Bb = bh3; P = pb3; break;
        }
        P[jj] = make_float4(A[jj] + Bb[jj], A[jj + 512] + Bb[jj + 512],
                            A[jj + 1024] + Bb[jj + 1024], A[jj + 1536] + Bb[jj + 1536]);
    }
}

__global__ void combine_dec0_kernel(
    const float* __restrict__ dWih0, const float* __restrict__ fcW,
    const float* __restrict__ dbih0, const float* __restrict__ dbhh0,
    const float* __restrict__ fcb,
    float4* __restrict__ Pc, float4* __restrict__ pbc)
{
    int idx = blockIdx.x * 256 + threadIdx.x;
    if (idx >= HH * 256) return;
    int jj = idx >> 8, h = (idx & 255) * 2;
    float si0 = 0, si1 = 0, sf0 = 0, sf1 = 0, sg0 = 0, sg1 = 0, so0 = 0, so1 = 0;
#pragma unroll 4
    for (int n = 0; n < FF; n++) {
        float f0 = fcW[n * HH + h], f1 = fcW[n * HH + h + 1];
        float wi = dWih0[jj * FF + n];
        float wf = dWih0[(jj + 512) * FF + n];
        float wg = dWih0[(jj + 1024) * FF + n];
        float wo = dWih0[(jj + 1536) * FF + n];
        si0 += wi * f0; si1 += wi * f1;
        sf0 += wf * f0; sf1 += wf * f1;
        sg0 += wg * f0; sg1 += wg * f1;
        so0 += wo * f0; so1 += wo * f1;
    }
    Pc[idx * 2 + 0] = make_float4(si0, si1, sf0, sf1);
    Pc[idx * 2 + 1] = make_float4(sg0, sg1, so0, so1);
    if ((idx & 255) == 0) {
        float bi = dbih0[jj] + dbhh0[jj];
        float bf = dbih0[jj + 512] + dbhh0[jj + 512];
        float bg = dbih0[jj + 1024] + dbhh0[jj + 1024];
        float bo = dbih0[jj + 1536] + dbhh0[jj + 1536];
#pragma unroll 4
        for (int n = 0; n < FF; n++) {
            float f = fcb[n];
            bi += dWih0[jj * FF + n] * f;
            bf += dWih0[(jj + 512) * FF + n] * f;
            bg += dWih0[(jj + 1024) * FF + n] * f;
            bo += dWih0[(jj + 1536) * FF + n] * f;
        }
        pbc[jj] = make_float4(bi, bf, bg, bo);
    }
}

__global__ void init_kernel(float* zerobuf) {
    int i = blockIdx.x * 256 + threadIdx.x;
    if (i < BH) zerobuf[i] = 0.f;
    if (i < NBLK * 8) g_flag[i] = 0;
    if (i == 0) g_bgen = 0;
}
__global__ void reset_bar_kernel() {
    int i = threadIdx.x;
    if (i < NBLK * 8) g_flag[i] = 0;
    if (i == 0) g_bgen = 0;
}

__global__ void final_fc_kernel(const float* __restrict__ h1hist, const float* __restrict__ fcW,
                                const float* __restrict__ fcb, float* __restrict__ out) {
    int t = blockIdx.y;
    int lx = blockIdx.x * 256 + threadIdx.x;
    int b = lx >> 6, n = lx & 63;
    const float4* h4 = (const float4*)(h1hist + ((size_t)t * BB + b) * HH);
    const float4* w4 = (const float4*)(fcW + (size_t)n * HH);
    float acc = fcb[n];
#pragma unroll 8
    for (int k = 0; k < HH / 4; k++) {
        float4 a = h4[k], ww = w4[k];
        acc += a.x * ww.x + a.y * ww.y + a.z * ww.z + a.w * ww.w;
    }
    out[((size_t)b * FUT + t) * FF + n] = acc;
}

// ---------------- host ----------------
extern "C" void kernel_launch(void* const* d_in, const int* in_sizes, int n_in,
                              void* d_out, int out_size) {
    const float* in_seq = (const float*)d_in[0];
    const float* eWih0  = (const float*)d_in[1];
    const float* eWhh0  = (const float*)d_in[2];
    const float* ebih0  = (const float*)d_in[3];
    const float* ebhh0  = (const float*)d_in[4];
    const float* eWih1  = (const float*)d_in[5];
    const float* eWhh1  = (const float*)d_in[6];
    const float* ebih1  = (const float*)d_in[7];
    const float* ebhh1  = (const float*)d_in[8];
    const float* dWih0  = (const float*)d_in[9];
    const float* dWhh0  = (const float*)d_in[10];
    const float* dbih0  = (const float*)d_in[11];
    const float* dbhh0  = (const float*)d_in[12];
    const float* dWih1  = (const float*)d_in[13];
    const float* dWhh1  = (const float*)d_in[14];
    const float* dbih1  = (const float*)d_in[15];
    const float* dbhh1  = (const float*)d_in[16];
    const float* fcW    = (const float*)d_in[17];
    const float* fcb    = (const float*)d_in[18];
    float* out = (float*)d_out;

    static int s_attr_done = 0;
    if (!s_attr_done) {
        cudaFuncSetAttribute(enc_kernel, cudaFuncAttributeMaxDynamicSharedMemorySize, ENC_SMEM);
        cudaFuncSetAttribute(dec_kernel, cudaFuncAttributeMaxDynamicSharedMemorySize, DEC_SMEM);
        s_attr_done = 1;
    }

    float4 *pWeih0, *pWehh0, *pWeih1, *pWehh1, *pWdih0, *pWdhh0, *pWdih1, *pWdhh1, *pWd0c;
    float4 *pbE0, *pbE1, *pbD0, *pbD1, *pbD0c;
    float *y0, *h1hist, *zerobuf, *c0, *c1, *h1A, *h1B, *h0A, *h0B;
    cudaGetSymbolAddress((void**)&y0,      g_y0);
    cudaGetSymbolAddress((void**)&h1hist,  g_h1hist);
    cudaGetSymbolAddress((void**)&zerobuf, g_zero);
    cudaGetSymbolAddress((void**)&c0,      g_c0);
    cudaGetSymbolAddress((void**)&c1,      g_c1);
    cudaGetSymbolAddress((void**)&h1A,     g_h1A);
    cudaGetSymbolAddress((void**)&h1B,     g_h1B);
    cudaGetSymbolAddress((void**)&h0A,     g_h0A);
    cudaGetSymbolAddress((void**)&h0B,     g_h0B);
    cudaGetSymbolAddress((void**)&pWeih0,  g_pW_enc_ih0);
    cudaGetSymbolAddress((void**)&pWehh0,  g_pW_enc_hh0);
    cudaGetSymbolAddress((void**)&pWeih1,  g_pW_enc_ih1);
    cudaGetSymbolAddress((void**)&pWehh1,  g_pW_enc_hh1);
    cudaGetSymbolAddress((void**)&pWdih0,  g_pW_dec_ih0);
    cudaGetSymbolAddress((void**)&pWdhh0,  g_pW_dec_hh0);
    cudaGetSymbolAddress((void**)&pWdih1,  g_pW_dec_ih1);
    cudaGetSymbolAddress((void**)&pWdhh1,  g_pW_dec_hh1);
    cudaGetSymbolAddress((void**)&pWd0c,   g_pW_dec0c);
    cudaGetSymbolAddress((void**)&pbE0,    g_pb_enc0);
    cudaGetSymbolAddress((void**)&pbE1,    g_pb_enc1);
    cudaGetSymbolAddress((void**)&pbD0,    g_pb_dec0);
    cudaGetSymbolAddress((void**)&pbD1,    g_pb_dec1);
    cudaGetSymbolAddress((void**)&pbD0c,   g_pb_dec0c);

    // Launch order: 2 harness pre-launches + [pack, combine, init, enc] -> enc at idx 5.
    {
        dim3 grid(512, 9);
        pack_all_kernel<<<grid, 256>>>(
            eWih0, eWhh0, eWih1, eWhh1, dWih0, dWhh0, dWih1, dWhh1,
            pWeih0, pWehh0, pWeih1, pWehh1, pWdih0, pWdhh0, pWdih1, pWdhh1,
            ebih0, ebhh0, ebih1, ebhh1, dbih0, dbhh0, dbih1, dbhh1,
            pbE0, pbE1, pbD0, pbD1);
    }
    combine_dec0_kernel<<<(HH * 256 + 255) / 256, 256>>>(
        dWih0, fcW, dbih0, dbhh0, fcb, pWd0c, pbD0c);
    init_kernel<<<(BH + 255) / 256, 256>>>(zerobuf);

    enc_kernel<<<NBLK, NTHR, ENC_SMEM>>>(
        in_seq, pWeih0, pWehh0, pWeih1, pWehh1, pbE0, pbE1,
        zerobuf, y0, h1A, h1B, c0, c1);

    reset_bar_kernel<<<1, 1024>>>();

    dec_kernel<<<NBLK, NTHR, DEC_SMEM>>>(
        in_seq, pWdih0, pWd0c, pWdhh0, pWdih1, pWdhh1,
        pbD0, pbD0c, pbD1,
        y0 + (size_t)(TT - 1) * BH,
        h1A,
        c0, c1, h0A, h0B, h1hist);

    {
        dim3 grid(16, FUT);
        final_fc_kernel<<<grid, 256>>>(h1hist, fcW, fcb, out);
    }
}

// round 17
// speedup vs baseline: 1.3544x; 1.2426x over previous
#include <cuda_runtime.h>

// LSTM seq2seq: B=64, T=512, F=64, H=512, FUT=96 — persistent v11.
// = v5 (best 14559us) + K-split across two warp-sets (256 thr):
//   warps 0-3 compute k [0,256), warps 4-7 k [256,512) with IDENTICAL per-warp
//   memory patterns (same staged buffer, +32-float / +32-u2 offsets).
//   2 warps/SMSP halves exposed LDS latency (the real binder: occ was 6%).
//   Set 1 accumulates from zero; smem merge (stride-17 u64) + set-0 finalize.

#define BB 64
#define TT 512
#define FF 64
#define HH 512
#define FUT 96
#define BH (BB*HH)          // 32768

#define NBLK 128
#define NTHR 256
#define WSS   514           // u2 per j row (K=512)
#define WSS64 66            // u2 per j row (K=64)
#define HSP 68              // floats per staged act row
#define HSBUF (64*HSP)      // 4352 floats = 17408 B per buffer

typedef unsigned long long u64;

// ---------------- device scratch ----------------
__device__ float  g_y0[TT*BB*HH];
__device__ float  g_h1hist[FUT*BB*HH];
__device__ float  g_zero[BH];
__device__ float  g_c0[BH], g_c1[BH];
__device__ float  g_h1A[BH], g_h1B[BH], g_h0A[BH], g_h0B[BH];

// pair-packed weights: per (j,k2): float4 {i(k),i(k+1),f(k),f(k+1)}, {g..,o..}
__device__ float4 g_pW_enc_ih0[HH*FF];
__device__ float4 g_pW_enc_hh0[HH*HH];
__device__ float4 g_pW_enc_ih1[HH*HH];
__device__ float4 g_pW_enc_hh1[HH*HH];
__device__ float4 g_pW_dec_ih0[HH*FF];
__device__ float4 g_pW_dec_hh0[HH*HH];
__device__ float4 g_pW_dec_ih1[HH*HH];
__device__ float4 g_pW_dec_hh1[HH*HH];
__device__ float4 g_pW_dec0c[HH*HH];
__device__ float4 g_pb_enc0[HH], g_pb_enc1[HH], g_pb_dec0[HH], g_pb_dec1[HH], g_pb_dec0c[HH];

__device__ unsigned g_bgen;
__device__ unsigned g_flag[NBLK*8];

// ---------------- f32x2 helpers ----------------
__device__ __forceinline__ u64 pack2(float a, float b) {
    u64 r;
    asm("mov.b64 %0, {%1, %2};" : "=l"(r) : "r"(__float_as_uint(a)), "r"(__float_as_uint(b)));
    return r;
}
__device__ __forceinline__ float2 unpack2(u64 v) {
    unsigned int lo, hi;
    asm("mov.b64 {%0, %1}, %2;" : "=r"(lo), "=r"(hi) : "l"(v));
    return make_float2(__uint_as_float(lo), __uint_as_float(hi));
}
__device__ __forceinline__ void ffma2(u64& d, u64 a, u64 b) {
    asm("fma.rn.f32x2 %0, %1, %2, %0;" : "+l"(d) : "l"(a), "l"(b));
}
__device__ __forceinline__ void fadd2(u64& d, u64 a) {
    asm("add.rn.f32x2 %0, %0, %1;" : "+l"(d) : "l"(a));
}

// ---------------- flag-tree grid barrier ----------------
__device__ __forceinline__ void grid_barrier(unsigned gen) {
    __syncthreads();
    int tid = threadIdx.x;
    if (blockIdx.x == 0) {
        if (tid > 0 && tid < NBLK) {
            unsigned v;
            do {
                asm volatile("ld.acquire.gpu.u32 %0, [%1];" : "=r"(v) : "l"(&g_flag[tid * 8]));
            } while (v < gen);
        }
        __syncthreads();
        if (tid == 0) {
            asm volatile("st.release.gpu.u32 [%0], %1;" :: "l"(&g_bgen), "r"(gen));
        }
    } else {
        if (tid == 0) {
            asm volatile("st.release.gpu.u32 [%0], %1;" :: "l"(&g_flag[blockIdx.x * 8]), "r"(gen));
            unsigned v;
            do {
                asm volatile("ld.acquire.gpu.u32 %0, [%1];" : "=r"(v) : "l"(&g_bgen));
            } while (v < gen);
        }
        __syncthreads();
    }
}

// ---------------- half-chunk compute (16 k2 = 32 k), 2 rows per thread ----------------
// A[0..3] = row0 gates i,f,g,o (u64 = 2 k-lanes); A[4..7] = row1. v5 pattern.
__device__ __forceinline__ void chunk16(
    u64* __restrict__ A, const ulonglong2* __restrict__ w,
    const float* __restrict__ h0, const float* __restrict__ h1)
{
#pragma unroll
    for (int k2 = 0; k2 < 16; k2 += 2) {
        ulonglong2 a = *(const ulonglong2*)(h0 + k2 * 2);
        ulonglong2 b = *(const ulonglong2*)(h1 + k2 * 2);
        ulonglong2 wif0 = w[2 * k2 + 0];
        ulonglong2 wgo0 = w[2 * k2 + 1];
        ulonglong2 wif1 = w[2 * k2 + 2];
        ulonglong2 wgo1 = w[2 * k2 + 3];
        ffma2(A[0], a.x, wif0.x); ffma2(A[1], a.x, wif0.y);
        ffma2(A[2], a.x, wgo0.x); ffma2(A[3], a.x, wgo0.y);
        ffma2(A[4], b.x, wif0.x); ffma2(A[5], b.x, wif0.y);
        ffma2(A[6], b.x, wgo0.x); ffma2(A[7], b.x, wgo0.y);
        ffma2(A[0], a.y, wif1.x); ffma2(A[1], a.y, wif1.y);
        ffma2(A[2], a.y, wgo1.x); ffma2(A[3], a.y, wgo1.y);
        ffma2(A[4], b.y, wif1.x); ffma2(A[5], b.y, wif1.y);
        ffma2(A[6], b.y, wgo1.x); ffma2(A[7], b.y, wgo1.y);
    }
}
__device__ __forceinline__ void chunk16_dual(
    u64* __restrict__ A, u64* __restrict__ B,
    const ulonglong2* __restrict__ wa, const ulonglong2* __restrict__ wb,
    const float* __restrict__ h0, const float* __restrict__ h1)
{
#pragma unroll
    for (int k2 = 0; k2 < 16; k2++) {
        u64 a = *(const u64*)(h0 + k2 * 2);
        u64 b = *(const u64*)(h1 + k2 * 2);
        ulonglong2 waif = wa[2 * k2], wago = wa[2 * k2 + 1];
        ulonglong2 wbif = wb[2 * k2], wbgo = wb[2 * k2 + 1];
        ffma2(A[0], a, waif.x); ffma2(A[1], a, waif.y);
        ffma2(A[2], a, wago.x); ffma2(A[3], a, wago.y);
        ffma2(A[4], b, waif.x); ffma2(A[5], b, waif.y);
        ffma2(A[6], b, wago.x); ffma2(A[7], b, wago.y);
        ffma2(B[0], a, wbif.x); ffma2(B[1], a, wbif.y);
        ffma2(B[2], a, wbgo.x); ffma2(B[3], a, wbgo.y);
        ffma2(B[4], b, wbif.x); ffma2(B[5], b, wbif.y);
        ffma2(B[6], b, wbgo.x); ffma2(B[7], b, wbgo.y);
    }
}

// ---------------- staged K=512 phases (256 threads stage; both sets compute) ----------------
// Staging: rbase = tid>>4 (0..15), c4 = tid&15; rows rbase + u*16, u<4.
// Compute: jl = (tid>>0)&3 ... set = tid>>7; set s takes k-offset s*32 floats / s*32 u2.
__device__ __forceinline__ void phase512_single(
    u64* __restrict__ A,
    const float* __restrict__ x, const ulonglong2* __restrict__ W,
    float* hs, int tid, int jl, int rh, int ks32)
{
    const float4* x4 = (const float4*)x;
    int rbase = tid >> 4, c4 = tid & 15;
    float4 pf[4];
#pragma unroll
    for (int u = 0; u < 4; u++) pf[u] = x4[(rbase + u * 16) * 128 + c4];
#pragma unroll 1
    for (int kc = 0; kc < HH; kc += 64) {
        float* buf = hs + ((kc >> 6) & 1) * HSBUF;
        float4* buf4 = (float4*)buf;
#pragma unroll
        for (int u = 0; u < 4; u++) buf4[(rbase + u * 16) * 17 + c4] = pf[u];
        __syncthreads();
        if (kc + 64 < HH) {
            int k4 = (kc + 64) >> 2;
#pragma unroll
            for (int u = 0; u < 4; u++) pf[u] = x4[(rbase + u * 16) * 128 + k4 + c4];
        }
        chunk16(A, W + jl * WSS + kc + ks32,
                buf + rh * HSP + ks32, buf + (rh + 32) * HSP + ks32);
    }
}
__device__ __forceinline__ void phase512_dual(
    u64* __restrict__ A, u64* __restrict__ B,
    const float* __restrict__ x,
    const ulonglong2* __restrict__ Wa, const ulonglong2* __restrict__ Wb,
    float* hs, int tid, int jl, int rh, int ks32)
{
    const float4* x4 = (const float4*)x;
    int rbase = tid >> 4, c4 = tid & 15;
    float4 pf[4];
#pragma unroll
    for (int u = 0; u < 4; u++) pf[u] = x4[(rbase + u * 16) * 128 + c4];
#pragma unroll 1
    for (int kc = 0; kc < HH; kc += 64) {
        float* buf = hs + ((kc >> 6) & 1) * HSBUF;
        float4* buf4 = (float4*)buf;
#pragma unroll
        for (int u = 0; u < 4; u++) buf4[(rbase + u * 16) * 17 + c4] = pf[u];
        __syncthreads();
        if (kc + 64 < HH) {
            int k4 = (kc + 64) >> 2;
#pragma unroll
            for (int u = 0; u < 4; u++) pf[u] = x4[(rbase + u * 16) * 128 + k4 + c4];
        }
        chunk16_dual(A, B, Wa + jl * WSS + kc + ks32, Wb + jl * WSS + kc + ks32,
                     buf + rh * HSP + ks32, buf + (rh + 32) * HSP + ks32);
    }
}
// K=64 phase: set 0 covers k 0..31, set 1 k 32..63 (split, same buffer).
__device__ __forceinline__ void phase64_single(
    u64* __restrict__ A, const float* __restrict__ x, long xs4,
    const ulonglong2* __restrict__ W, float* hs, int tid, int jl, int rh, int ks32)
{
    const float4* x4 = (const float4*)x;
    int rbase = tid >> 4, c4 = tid & 15;
    float* buf = hs + HSBUF;    // buffer 1 (parity-safe vs phase512 start)
    float4* buf4 = (float4*)buf;
#pragma unroll
    for (int u = 0; u < 4; u++)
        buf4[(rbase + u * 16) * 17 + c4] = x4[(long)(rbase + u * 16) * xs4 + c4];
    __syncthreads();
    chunk16(A, W + jl * WSS64 + ks32,
            buf + rh * HSP + ks32, buf + (rh + 32) * HSP + ks32);
}

__device__ __forceinline__ float cellfin4(u64 gi2, u64 gf2, u64 gg2, u64 go2, float& c) {
    float2 vi = unpack2(gi2), vf = unpack2(gf2), vg = unpack2(gg2), vo = unpack2(go2);
    float gi = vi.x + vi.y, gf = vf.x + vf.y, gg = vg.x + vg.y, go = vo.x + vo.y;
    float si = 1.f / (1.f + __expf(-gi));
    float sf = 1.f / (1.f + __expf(-gf));
    float so = 1.f / (1.f + __expf(-go));
    float cn = sf * c + si * tanhf(gg);
    c = cn;
    return so * tanhf(cn);
}
__device__ __forceinline__ void bias_init(u64* A, float4 b) {
    A[0] = pack2(b.x, 0.f); A[1] = pack2(b.y, 0.f);
    A[2] = pack2(b.z, 0.f); A[3] = pack2(b.w, 0.f);
    A[4] = A[0]; A[5] = A[1]; A[6] = A[2]; A[7] = A[3];
}
__device__ __forceinline__ void zero8(u64* A) {
#pragma unroll
    for (int i = 0; i < 8; i++) A[i] = 0ULL;
}

#define ENC_SMEM ((3*4*WSS + 4*WSS64) * 16 + 2*HSBUF*4)
#define DEC_SMEM ((4*4*WSS + 4*WSS64) * 16 + 2*HSBUF*4)

// ---------------- persistent encoder: L0 + L1 software-pipelined ----------------
__global__ void __launch_bounds__(NTHR, 1) enc_kernel(
    const float* __restrict__ in_seq,
    const float4* __restrict__ pW0x, const float4* __restrict__ pW0h,
    const float4* __restrict__ pW1x, const float4* __restrict__ pW1h,
    const float4* __restrict__ pb0, const float4* __restrict__ pb1,
    const float* __restrict__ zerobuf,
    float* __restrict__ y0, float* __restrict__ h1A, float* __restrict__ h1B,
    float* __restrict__ c0out, float* __restrict__ c1out)
{
    extern __shared__ __align__(16) unsigned char smraw[];
    ulonglong2* W0h = (ulonglong2*)smraw;
    ulonglong2* W1x = W0h + 4 * WSS;
    ulonglong2* W1h = W1x + 4 * WSS;
    ulonglong2* W0x = W1h + 4 * WSS;
    float* hs = (float*)(W0x + 4 * WSS64);
    u64* mrg = (u64*)hs;            // merge area aliases staging buffer 0

    int tid = threadIdx.x;
    int lt = tid & 127;             // lane within set
    int kset = tid >> 7;            // 0 or 1
    int ks32 = kset * 32;
    int jl = lt & 3, rh = lt >> 2;  // v5 mapping per set
    int j0 = blockIdx.x * 4, j = j0 + jl;
    int idx0 = (rh << 9) + j;
    int idx1 = ((rh + 32) << 9) + j;

    {   // load weight tiles (once)
        const ulonglong2* g0h = (const ulonglong2*)pW0h + (size_t)j0 * HH;
        const ulonglong2* g1x = (const ulonglong2*)pW1x + (size_t)j0 * HH;
        const ulonglong2* g1h = (const ulonglong2*)pW1h + (size_t)j0 * HH;
#pragma unroll 2
        for (int i = tid; i < 4 * HH; i += NTHR) {
            int jj = i >> 9, kk = i & 511;
            W0h[jj * WSS + kk] = g0h[i];
            W1x[jj * WSS + kk] = g1x[i];
            W1h[jj * WSS + kk] = g1h[i];
        }
        const ulonglong2* g0x = (const ulonglong2*)pW0x + (size_t)j0 * FF;
#pragma unroll
        for (int i = tid; i < 4 * FF; i += NTHR) {
            int jj = i >> 6, kk = i & 63;
            W0x[jj * WSS64 + kk] = g0x[i];
        }
    }
    float4 b0 = pb0[j], b1 = pb1[j];
    float c0a = 0.f, c0b = 0.f, c1a = 0.f, c1b = 0.f;
    __syncthreads();

    unsigned gen = 0;
    for (int slot = 0; slot <= TT; slot++) {
        bool doL0 = (slot < TT);
        bool doL1 = (slot > 0);
        const float* yprev = (slot == 0) ? zerobuf : (y0 + (size_t)(slot - 1) * BH);

        u64 A[8], B[8];
        if (kset == 0) { bias_init(A, b0); bias_init(B, b1); }
        else           { zero8(A); zero8(B); }

        if (doL0)
            phase64_single(A, in_seq + (size_t)slot * FF, (long)TT * FF / 4, W0x,
                           hs, tid, jl, rh, ks32);

        if (doL0 && doL1)
            phase512_dual(A, B, yprev, W0h, W1x, hs, tid, jl, rh, ks32);
        else if (doL0)
            phase512_single(A, yprev, W0h, hs, tid, jl, rh, ks32);
        else
            phase512_single(B, yprev, W1x, hs, tid, jl, rh, ks32);

        if (doL1) {
            const float* h1p = (slot == 1) ? zerobuf : ((slot & 1) ? h1A : h1B);
            phase512_single(B, h1p, W1h, hs, tid, jl, rh, ks32);
        }

        // ---- merge sets, finalize in set 0 ----
        __syncthreads();
        if (kset) {
            u64* m = mrg + lt * 17;
#pragma unroll
            for (int i = 0; i < 8; i++) { m[i] = A[i]; m[8 + i] = B[i]; }
        }
        __syncthreads();
        if (!kset) {
            const u64* m = mrg + lt * 17;
#pragma unroll
            for (int i = 0; i < 8; i++) { fadd2(A[i], m[i]); fadd2(B[i], m[8 + i]); }
            if (doL1) {
                float* h1o = (slot & 1) ? h1B : h1A;
                h1o[idx0] = cellfin4(B[0], B[1], B[2], B[3], c1a);
                h1o[idx1] = cellfin4(B[4], B[5], B[6], B[7], c1b);
            }
            if (doL0) {
                float* yo = y0 + (size_t)slot * BH;
                yo[idx0] = cellfin4(A[0], A[1], A[2], A[3], c0a);
                yo[idx1] = cellfin4(A[4], A[5], A[6], A[7], c0b);
            }
        }

        if (slot < TT) {
            gen++;
            grid_barrier(gen);      // includes __syncthreads: protects mrg/buffers
        }
    }
    if (!kset) {
        c0out[idx0] = c0a; c0out[idx1] = c0b;
        c1out[idx0] = c1a; c1out[idx1] = c1b;
    }
    // final h1 at slot TT (even) -> h1A
}

// ---------------- persistent decoder ----------------
__global__ void __launch_bounds__(NTHR, 1) dec_kernel(
    const float* __restrict__ in_seq,
    const float4* __restrict__ pWd0x, const float4* __restrict__ pWd0c,
    const float4* __restrict__ pWdh0, const float4* __restrict__ pWdx1,
    const float4* __restrict__ pWdh1,
    const float4* __restrict__ pbD0, const float4* __restrict__ pbD0c,
    const float4* __restrict__ pbD1,
    const float* __restrict__ h0init, const float* __restrict__ h1init,
    const float* __restrict__ c0in, const float* __restrict__ c1in,
    float* __restrict__ h0A, float* __restrict__ h0B, float* __restrict__ h1hist)
{
    extern __shared__ __align__(16) unsigned char smraw[];
    ulonglong2* Wc  = (ulonglong2*)smraw;
    ulonglong2* Wh0 = Wc  + 4 * WSS;
    ulonglong2* Wx1 = Wh0 + 4 * WSS;
    ulonglong2* Wh1 = Wx1 + 4 * WSS;
    ulonglong2* W0x = Wh1 + 4 * WSS;
    float* hs = (float*)(W0x + 4 * WSS64);
    u64* mrg = (u64*)hs;

    int tid = threadIdx.x;
    int lt = tid & 127;
    int kset = tid >> 7;
    int ks32 = kset * 32;
    int jl = lt & 3, rh = lt >> 2;
    int j0 = blockIdx.x * 4, j = j0 + jl;
    int idx0 = (rh << 9) + j;
    int idx1 = ((rh + 32) << 9) + j;

    {
        const ulonglong2* gc  = (const ulonglong2*)pWd0c + (size_t)j0 * HH;
        const ulonglong2* gh0 = (const ulonglong2*)pWdh0 + (size_t)j0 * HH;
        const ulonglong2* gx1 = (const ulonglong2*)pWdx1 + (size_t)j0 * HH;
        const ulonglong2* gh1 = (const ulonglong2*)pWdh1 + (size_t)j0 * HH;
#pragma unroll 2
        for (int i = tid; i < 4 * HH; i += NTHR) {
            int jj = i >> 9, kk = i & 511;
            Wc[jj * WSS + kk]  = gc[i];
            Wh0[jj * WSS + kk] = gh0[i];
            Wx1[jj * WSS + kk] = gx1[i];
            Wh1[jj * WSS + kk] = gh1[i];
        }
        const ulonglong2* g0x = (const ulonglong2*)pWd0x + (size_t)j0 * FF;
#pragma unroll
        for (int i = tid; i < 4 * FF; i += NTHR) {
            int jj = i >> 6, kk = i & 63;
            W0x[jj * WSS64 + kk] = g0x[i];
        }
    }
    float4 bd0 = pbD0[j], bd0c = pbD0c[j], bd1 = pbD1[j];
    float c0a = c0in[idx0], c0b = c0in[idx1];
    float c1a = c1in[idx0], c1b = c1in[idx1];
    __syncthreads();

    unsigned gen = 0;
    const float* h0prev = h0init;
    const float* h1prev = h1init;

    for (int t = 0; t < FUT; t++) {
        // ---- cell d0 ----
        u64 A[8];
        if (t == 0) {
            if (kset == 0) bias_init(A, bd0); else zero8(A);
            phase64_single(A, in_seq + (size_t)(TT - 1) * FF, (long)TT * FF / 4,
                           W0x, hs, tid, jl, rh, ks32);
        } else {
            if (kset == 0) bias_init(A, bd0c); else zero8(A);
            phase512_single(A, h1hist + (size_t)(t - 1) * BH, Wc, hs, tid, jl, rh, ks32);
        }
        phase512_single(A, h0prev, Wh0, hs, tid, jl, rh, ks32);
        __syncthreads();
        if (kset) {
            u64* m = mrg + lt * 17;
#pragma unroll
            for (int i = 0; i < 8; i++) m[i] = A[i];
        }
        __syncthreads();
        float* h0out = (t & 1) ? h0B : h0A;
        if (!kset) {
            const u64* m = mrg + lt * 17;
#pragma unroll
            for (int i = 0; i < 8; i++) fadd2(A[i], m[i]);
            h0out[idx0] = cellfin4(A[0], A[1], A[2], A[3], c0a);
            h0out[idx1] = cellfin4(A[4], A[5], A[6], A[7], c0b);
        }
        gen++; grid_barrier(gen);

        // ---- cell d1 ----
        u64 R[8];
        if (kset == 0) bias_init(R, bd1); else zero8(R);
        phase512_single(R, h0out, Wx1, hs, tid, jl, rh, ks32);
        phase512_single(R, h1prev, Wh1, hs, tid, jl, rh, ks32);
        __syncthreads();
        if (kset) {
            u64* m = mrg + lt * 17;
#pragma unroll
            for (int i = 0; i < 8; i++) m[i] = R[i];
        }
        __syncthreads();
        float* h1o = h1hist + (size_t)t * BH;
        if (!kset) {
            const u64* m = mrg + lt * 17;
#pragma unroll
            for (int i = 0; i < 8; i++) fadd2(R[i], m[i]);
            h1o[idx0] = cellfin4(R[0], R[1], R[2], R[3], c1a);
            h1o[idx1] = cellfin4(R[4], R[5], R[6], R[7], c1b);
        }
        if (t < FUT - 1) { gen++; grid_barrier(gen); }
        else __syncthreads();
        h0prev = h0out;
        h1prev = h1o;
    }
}

// ---------------- setup kernels (v5 verbatim) ----------------
__global__ void pack_all_kernel(
    const float* __restrict__ s0, const float* __restrict__ s1,
    const float* __restrict__ s2, const float* __restrict__ s3,
    const float* __restrict__ s4, const float* __restrict__ s5,
    const float* __restrict__ s6, const float* __restrict__ s7,
    float4* __restrict__ d0, float4* __restrict__ d1,
    float4* __restrict__ d2, float4* __restrict__ d3,
    float4* __restrict__ d4, float4* __restrict__ d5,
    float4* __restrict__ d6, float4* __restrict__ d7,
    const float* __restrict__ bi0, const float* __restrict__ bh0,
    const float* __restrict__ bi1, const float* __restrict__ bh1,
    const float* __restrict__ bi2, const float* __restrict__ bh2,
    const float* __restrict__ bi3, const float* __restrict__ bh3,
    float4* __restrict__ pb0, float4* __restrict__ pb1,
    float4* __restrict__ pb2, float4* __restrict__ pb3)
{
    int m = blockIdx.y;
    int idx = blockIdx.x * 256 + threadIdx.x;
    if (m < 8) {
        const float* S; float4* D; int Kin;
        switch (m) {
            case 0: S = s0; D = d0; Kin = FF; break;
            case 1: S = s1; D = d1; Kin = HH; break;
            case 2: S = s2; D = d2; Kin = HH; break;
            case 3: S = s3; D = d3; Kin = HH; break;
            case 4: S = s4; D = d4; Kin = FF; break;
            case 5: S = s5; D = d5; Kin = HH; break;
            case 6: S = s6; D = d6; Kin = HH; break;
            default: S = s7; D = d7; Kin = HH; break;
        }
        int K2 = Kin >> 1;
        if (idx >= HH * K2) return;
        int jj = idx / K2, k2 = idx - jj * K2;
        int k = k2 * 2;
        D[idx * 2 + 0] = make_float4(S[jj * Kin + k], S[jj * Kin + k + 1],
                                     S[(jj + 512) * Kin + k], S[(jj + 512) * Kin + k + 1]);
        D[idx * 2 + 1] = make_float4(S[(jj + 1024) * Kin + k], S[(jj + 1024) * Kin + k + 1],
                                     S[(jj + 1536) * Kin + k], S[(jj + 1536) * Kin + k + 1]);
    } else {
        if (idx >= 4 * HH) return;
        int which = idx >> 9, jj = idx & 511;
        const float* A; const float* Bb; float4* P;
        switch (which) {
            case 0: A = bi0; Bb = bh0; P = pb0; break;
            case 1: A = bi1; Bb = bh1; P = pb1; break;
            case 2: A = bi2; Bb = bh2; P = pb2; break;
            default: A = bi3; Bb = bh3; P = pb3; break;
        }
        P[jj] = make_float4(A[jj] + Bb[jj], A[jj + 512] + Bb[jj + 512],
                            A[jj + 1024] + Bb[jj + 1024], A[jj + 1536] + Bb[jj + 1536]);
    }
}

__global__ void combine_dec0_kernel(
    const float* __restrict__ dWih0, const float* __restrict__ fcW,
    const float* __restrict__ dbih0, const float* __restrict__ dbhh0,
    const float* __restrict__ fcb,
    float4* __restrict__ Pc, float4* __restrict__ pbc)
{
    int idx = blockIdx.x * 256 + threadIdx.x;
    if (idx >= HH * 256) return;
    int jj = idx >> 8, h = (idx & 255) * 2;
    float si0 = 0, si1 = 0, sf0 = 0, sf1 = 0, sg0 = 0, sg1 = 0, so0 = 0, so1 = 0;
#pragma unroll 4
    for (int n = 0; n < FF; n++) {
        float f0 = fcW[n * HH + h], f1 = fcW[n * HH + h + 1];
        float wi = dWih0[jj * FF + n];
        float wf = dWih0[(jj + 512) * FF + n];
        float wg = dWih0[(jj + 1024) * FF + n];
        float wo = dWih0[(jj + 1536) * FF + n];
        si0 += wi * f0; si1 += wi * f1;
        sf0 += wf * f0; sf1 += wf * f1;
        sg0 += wg * f0; sg1 += wg * f1;
        so0 += wo * f0; so1 += wo * f1;
    }
    Pc[idx * 2 + 0] = make_float4(si0, si1, sf0, sf1);
    Pc[idx * 2 + 1] = make_float4(sg0, sg1, so0, so1);
    if ((idx & 255) == 0) {
        float bi = dbih0[jj] + dbhh0[jj];
        float bf = dbih0[jj + 512] + dbhh0[jj + 512];
        float bg = dbih0[jj + 1024] + dbhh0[jj + 1024];
        float bo = dbih0[jj + 1536] + dbhh0[jj + 1536];
#pragma unroll 4
        for (int n = 0; n < FF; n++) {
            float f = fcb[n];
            bi += dWih0[jj * FF + n] * f;
            bf += dWih0[(jj + 512) * FF + n] * f;
            bg += dWih0[(jj + 1024) * FF + n] * f;
            bo += dWih0[(jj + 1536) * FF + n] * f;
        }
        pbc[jj] = make_float4(bi, bf, bg, bo);
    }
}

__global__ void init_kernel(float* zerobuf) {
    int i = blockIdx.x * 256 + threadIdx.x;
    if (i < BH) zerobuf[i] = 0.f;
    if (i < NBLK * 8) g_flag[i] = 0;
    if (i == 0) g_bgen = 0;
}
__global__ void reset_bar_kernel() {
    int i = threadIdx.x;
    if (i < NBLK * 8) g_flag[i] = 0;
    if (i == 0) g_bgen = 0;
}

__global__ void final_fc_kernel(const float* __restrict__ h1hist, const float* __restrict__ fcW,
                                const float* __restrict__ fcb, float* __restrict__ out) {
    int t = blockIdx.y;
    int lx = blockIdx.x * 256 + threadIdx.x;
    int b = lx >> 6, n = lx & 63;
    const float4* h4 = (const float4*)(h1hist + ((size_t)t * BB + b) * HH);
    const float4* w4 = (const float4*)(fcW + (size_t)n * HH);
    float acc = fcb[n];
#pragma unroll 8
    for (int k = 0; k < HH / 4; k++) {
        float4 a = h4[k], ww = w4[k];
        acc += a.x * ww.x + a.y * ww.y + a.z * ww.z + a.w * ww.w;
    }
    out[((size_t)b * FUT + t) * FF + n] = acc;
}

// ---------------- host ----------------
extern "C" void kernel_launch(void* const* d_in, const int* in_sizes, int n_in,
                              void* d_out, int out_size) {
    const float* in_seq = (const float*)d_in[0];
    const float* eWih0  = (const float*)d_in[1];
    const float* eWhh0  = (const float*)d_in[2];
    const float* ebih0  = (const float*)d_in[3];
    const float* ebhh0  = (const float*)d_in[4];
    const float* eWih1  = (const float*)d_in[5];
    const float* eWhh1  = (const float*)d_in[6];
    const float* ebih1  = (const float*)d_in[7];
    const float* ebhh1  = (const float*)d_in[8];
    const float* dWih0  = (const float*)d_in[9];
    const float* dWhh0  = (const float*)d_in[10];
    const float* dbih0  = (const float*)d_in[11];
    const float* dbhh0  = (const float*)d_in[12];
    const float* dWih1  = (const float*)d_in[13];
    const float* dWhh1  = (const float*)d_in[14];
    const float* dbih1  = (const float*)d_in[15];
    const float* dbhh1  = (const float*)d_in[16];
    const float* fcW    = (const float*)d_in[17];
    const float* fcb    = (const float*)d_in[18];
    float* out = (float*)d_out;

    static int s_attr_done = 0;
    if (!s_attr_done) {
        cudaFuncSetAttribute(enc_kernel, cudaFuncAttributeMaxDynamicSharedMemorySize, ENC_SMEM);
        cudaFuncSetAttribute(dec_kernel, cudaFuncAttributeMaxDynamicSharedMemorySize, DEC_SMEM);
        s_attr_done = 1;
    }

    float4 *pWeih0, *pWehh0, *pWeih1, *pWehh1, *pWdih0, *pWdhh0, *pWdih1, *pWdhh1, *pWd0c;
    float4 *pbE0, *pbE1, *pbD0, *pbD1, *pbD0c;
    float *y0, *h1hist, *zerobuf, *c0, *c1, *h1A, *h1B, *h0A, *h0B;
    cudaGetSymbolAddress((void**)&y0,      g_y0);
    cudaGetSymbolAddress((void**)&h1hist,  g_h1hist);
    cudaGetSymbolAddress((void**)&zerobuf, g_zero);
    cudaGetSymbolAddress((void**)&c0,      g_c0);
    cudaGetSymbolAddress((void**)&c1,      g_c1);
    cudaGetSymbolAddress((void**)&h1A,     g_h1A);
    cudaGetSymbolAddress((void**)&h1B,     g_h1B);
    cudaGetSymbolAddress((void**)&h0A,     g_h0A);
    cudaGetSymbolAddress((void**)&h0B,     g_h0B);
    cudaGetSymbolAddress((void**)&pWeih0,  g_pW_enc_ih0);
    cudaGetSymbolAddress((void**)&pWehh0,  g_pW_enc_hh0);
    cudaGetSymbolAddress((void**)&pWeih1,  g_pW_enc_ih1);
    cudaGetSymbolAddress((void**)&pWehh1,  g_pW_enc_hh1);
    cudaGetSymbolAddress((void**)&pWdih0,  g_pW_dec_ih0);
    cudaGetSymbolAddress((void**)&pWdhh0,  g_pW_dec_hh0);
    cudaGetSymbolAddress((void**)&pWdih1,  g_pW_dec_ih1);
    cudaGetSymbolAddress((void**)&pWdhh1,  g_pW_dec_hh1);
    cudaGetSymbolAddress((void**)&pWd0c,   g_pW_dec0c);
    cudaGetSymbolAddress((void**)&pbE0,    g_pb_enc0);
    cudaGetSymbolAddress((void**)&pbE1,    g_pb_enc1);
    cudaGetSymbolAddress((void**)&pbD0,    g_pb_dec0);
    cudaGetSymbolAddress((void**)&pbD1,    g_pb_dec1);
    cudaGetSymbolAddress((void**)&pbD0c,   g_pb_dec0c);

    // Launch order: 2 harness pre-launches + [pack, combine, init, enc] -> enc at idx 5.
    {
        dim3 grid(512, 9);
        pack_all_kernel<<<grid, 256>>>(
            eWih0, eWhh0, eWih1, eWhh1, dWih0, dWhh0, dWih1, dWhh1,
            pWeih0, pWehh0, pWeih1, pWehh1, pWdih0, pWdhh0, pWdih1, pWdhh1,
            ebih0, ebhh0, ebih1, ebhh1, dbih0, dbhh0, dbih1, dbhh1,
            pbE0, pbE1, pbD0, pbD1);
    }
    combine_dec0_kernel<<<(HH * 256 + 255) / 256, 256>>>(
        dWih0, fcW, dbih0, dbhh0, fcb, pWd0c, pbD0c);
    init_kernel<<<(BH + 255) / 256, 256>>>(zerobuf);

    enc_kernel<<<NBLK, NTHR, ENC_SMEM>>>(
        in_seq, pWeih0, pWehh0, pWeih1, pWehh1, pbE0, pbE1,
        zerobuf, y0, h1A, h1B, c0, c1);

    reset_bar_kernel<<<1, 1024>>>();

    dec_kernel<<<NBLK, NTHR, DEC_SMEM>>>(
        in_seq, pWdih0, pWd0c, pWdhh0, pWdih1, pWdhh1,
        pbD0, pbD0c, pbD1,
        y0 + (size_t)(TT - 1) * BH,
        h1A,
        c0, c1, h0A, h0B, h1hist);

    {
        dim3 grid(16, FUT);
        final_fc_kernel<<<grid, 256>>>(h1hist, fcW, fcb, out);
    }
}